// round 5
// baseline (speedup 1.0000x reference)
#include <cuda_runtime.h>
#include <cstdint>

#define Bb 4
#define Ll 1024
#define Hh 128
#define Ee 128
#define Nn 128
#define ML (Bb*Ll)   // 4096
#define CH 32        // number of L-chunks
#define CS 32        // chunk size (CH*CS == Ll)

// ---------------- scratch (device globals: no allocations allowed) ----------------
__device__ float g_x[Bb*Ll*Ee];      // pre-conv x
__device__ float g_zs[Bb*Ll*Ee];     // silu(z)
__device__ float g_xc[Bb*Ll*Ee];     // post-conv silu(x)
__device__ float g_delta[Bb*Ll*Nn];  // softplus'd
__device__ float g_Braw[Bb*Ll*Nn];
__device__ float g_C[Bb*Ll*Hh];
__device__ float g_y[Bb*Ll*Hh];      // gated scan output (input to GEMM3)
__device__ float g_S[Bb*Ll*Hh];      // local (then full) n-sums
__device__ float g_cumd[Bb*Ll*Nn];   // within-chunk inclusive cumsum of delta [b][t][n]
__device__ float g_hE[Bb*CH*Nn*Hh];  // chunk-end local states [b][k][n][c]
__device__ float g_h0[Bb*CH*Nn*Hh];  // chunk-start true states [b][k][n][c]

__device__ __forceinline__ float silu_(float x){ return x / (1.f + __expf(-x)); }
__device__ __forceinline__ float softplus_(float x){ return x > 20.f ? x : log1pf(__expf(x)); }
__device__ __forceinline__ float ex2f(float x){ float r; asm("ex2.approx.ftz.f32 %0, %1;" : "=f"(r) : "f"(x)); return r; }

// ---------------- 3xTF32 tensor-core GEMM ----------------
// C[M,N] = A[M,128] @ W[128,N] + bias, fused epilogues.
// Block: 128(M) x 64(N), 256 threads = 8 warps in 4x2; warp tile 32x32 = 2x4 mma tiles.
__device__ __forceinline__ void split_tf32(float x, float& hi, float& lo) {
    uint32_t h; asm("cvt.rna.tf32.f32 %0, %1;" : "=r"(h) : "f"(x));
    float hf = __uint_as_float(h);
    float r = x - hf;
    uint32_t l; asm("cvt.rna.tf32.f32 %0, %1;" : "=r"(l) : "f"(r));
    hi = hf; lo = __uint_as_float(l);
}

__device__ __forceinline__ void mma_tf32(float* d, const float* a, const float* b) {
    asm volatile(
        "mma.sync.aligned.m16n8k8.row.col.f32.tf32.tf32.f32 "
        "{%0,%1,%2,%3}, {%4,%5,%6,%7}, {%8,%9}, {%0,%1,%2,%3};"
        : "+f"(d[0]), "+f"(d[1]), "+f"(d[2]), "+f"(d[3])
        : "r"(__float_as_uint(a[0])), "r"(__float_as_uint(a[1])),
          "r"(__float_as_uint(a[2])), "r"(__float_as_uint(a[3])),
          "r"(__float_as_uint(b[0])), "r"(__float_as_uint(b[1])));
}

template<int EPI>
__global__ __launch_bounds__(256) void gemm_tc(
    const float* __restrict__ Ap, const float* __restrict__ Wp,
    const float* __restrict__ bias, float* __restrict__ Cout, int ldN)
{
    __shared__ __align__(16) float Ah[128][20];   // k-chunk 16, pitch 20 (bank-clean frags)
    __shared__ __align__(16) float Al[128][20];
    __shared__ __align__(16) float Wh[16][68];    // pitch 68 (bank-clean frags)
    __shared__ __align__(16) float Wl[16][68];

    int tid = threadIdx.x;
    int w = tid >> 5, ln = tid & 31;
    int g = ln >> 2, t = ln & 3;
    int m0 = (w >> 1) * 32;          // warp M offset in block
    int n0 = (w & 1) * 32;           // warp N offset in block
    int row0 = blockIdx.x * 128;
    int col0 = blockIdx.y * 64;

    float acc[2][4][4];
    #pragma unroll
    for (int mt = 0; mt < 2; ++mt)
        #pragma unroll
        for (int nt = 0; nt < 4; ++nt)
            #pragma unroll
            for (int i = 0; i < 4; ++i) acc[mt][nt][i] = 0.f;

    #pragma unroll
    for (int kc = 0; kc < 128; kc += 16) {
        // stage A [128][16] split hi/lo (512 float4 slots)
        #pragma unroll
        for (int i = 0; i < 2; ++i) {
            int f = tid + i * 256;
            int r = f >> 2, q = f & 3;
            float4 v = *(const float4*)&Ap[(size_t)(row0 + r) * 128 + kc + q * 4];
            float4 vh, vl;
            split_tf32(v.x, vh.x, vl.x); split_tf32(v.y, vh.y, vl.y);
            split_tf32(v.z, vh.z, vl.z); split_tf32(v.w, vh.w, vl.w);
            *(float4*)&Ah[r][q * 4] = vh;
            *(float4*)&Al[r][q * 4] = vl;
        }
        // stage W [16][64] split hi/lo (256 float4 slots)
        {
            int k = tid >> 4, q = tid & 15;
            float4 v = *(const float4*)&Wp[(size_t)(kc + k) * ldN + col0 + q * 4];
            float4 vh, vl;
            split_tf32(v.x, vh.x, vl.x); split_tf32(v.y, vh.y, vl.y);
            split_tf32(v.z, vh.z, vl.z); split_tf32(v.w, vh.w, vl.w);
            *(float4*)&Wh[k][q * 4] = vh;
            *(float4*)&Wl[k][q * 4] = vl;
        }
        __syncthreads();

        #pragma unroll
        for (int ks = 0; ks < 16; ks += 8) {
            float ah[2][4], al[2][4], bh[4][2], bl[4][2];
            #pragma unroll
            for (int mt = 0; mt < 2; ++mt) {
                int r = m0 + mt * 16 + g;
                ah[mt][0] = Ah[r][ks + t];     ah[mt][1] = Ah[r + 8][ks + t];
                ah[mt][2] = Ah[r][ks + t + 4]; ah[mt][3] = Ah[r + 8][ks + t + 4];
                al[mt][0] = Al[r][ks + t];     al[mt][1] = Al[r + 8][ks + t];
                al[mt][2] = Al[r][ks + t + 4]; al[mt][3] = Al[r + 8][ks + t + 4];
            }
            #pragma unroll
            for (int nt = 0; nt < 4; ++nt) {
                int nn = n0 + nt * 8 + g;
                bh[nt][0] = Wh[ks + t][nn]; bh[nt][1] = Wh[ks + t + 4][nn];
                bl[nt][0] = Wl[ks + t][nn]; bl[nt][1] = Wl[ks + t + 4][nn];
            }
            #pragma unroll
            for (int mt = 0; mt < 2; ++mt)
                #pragma unroll
                for (int nt = 0; nt < 4; ++nt) {
                    mma_tf32(acc[mt][nt], ah[mt], bh[nt]);
                    mma_tf32(acc[mt][nt], ah[mt], bl[nt]);
                    mma_tf32(acc[mt][nt], al[mt], bh[nt]);
                }
        }
        __syncthreads();
    }

    // epilogue: c0:(g,2t) c1:(g,2t+1) c2:(g+8,2t) c3:(g+8,2t+1)
    #pragma unroll
    for (int mt = 0; mt < 2; ++mt) {
        #pragma unroll
        for (int nt = 0; nt < 4; ++nt) {
            int col = col0 + n0 + nt * 8 + 2 * t;
            float b0 = bias[col], b1 = bias[col + 1];
            #pragma unroll
            for (int half = 0; half < 2; ++half) {
                int row = row0 + m0 + mt * 16 + g + half * 8;
                float v0 = acc[mt][nt][half * 2 + 0] + b0;
                float v1 = acc[mt][nt][half * 2 + 1] + b1;
                if (EPI == 1) {
                    if (col < 128) {
                        g_x[(size_t)row * 128 + col] = v0;
                        g_x[(size_t)row * 128 + col + 1] = v1;
                    } else {
                        g_zs[(size_t)row * 128 + col - 128] = silu_(v0);
                        g_zs[(size_t)row * 128 + col - 127] = silu_(v1);
                    }
                } else if (EPI == 2) {
                    if (col < 128) {
                        g_delta[(size_t)row * 128 + col] = softplus_(v0);
                        g_delta[(size_t)row * 128 + col + 1] = softplus_(v1);
                    } else if (col < 256) {
                        g_Braw[(size_t)row * 128 + col - 128] = v0;
                        g_Braw[(size_t)row * 128 + col - 127] = v1;
                    } else {
                        g_C[(size_t)row * 128 + col - 256] = v0;
                        g_C[(size_t)row * 128 + col - 255] = v1;
                    }
                } else {
                    Cout[(size_t)row * 128 + col] = v0;
                    Cout[(size_t)row * 128 + col + 1] = v1;
                }
            }
        }
    }
}

// ---------------- depthwise conv3 (+bias, silu) ----------------
__global__ void conv_kernel(const float* __restrict__ cw, const float* __restrict__ cb)
{
    int idx = blockIdx.x * blockDim.x + threadIdx.x;
    if (idx >= Bb * Ll * Ee) return;
    int e = idx & 127;
    int t = (idx >> 7) & (Ll - 1);
    float w0 = cw[e * 3 + 0], w1 = cw[e * 3 + 1], w2 = cw[e * 3 + 2];
    float xm = g_x[idx];
    float xl = (t > 0)      ? g_x[idx - 128] : 0.f;
    float xr = (t < Ll - 1) ? g_x[idx + 128] : 0.f;
    float v = fmaf(w0, xl, fmaf(w1, xm, fmaf(w2, xr, cb[e])));
    g_xc[idx] = silu_(v);
}

// ---------------- Pass 1: per-chunk local scan (4n x 4c states per thread) ----------
__global__ __launch_bounds__(256) void scan_local_kernel(const float* __restrict__ A_log)
{
    __shared__ __align__(16) float smd[16][128];
    __shared__ __align__(16) float smb[16][128];
    __shared__ __align__(16) float smx[16][32];
    __shared__ float smP[4][32][33];

    int b  = blockIdx.z;
    int k  = blockIdx.y;
    int cg = blockIdx.x;
    int tid = threadIdx.x;
    int w = tid >> 5, ln = tid & 31;

    float Ac2[4];
    #pragma unroll
    for (int j = 0; j < 4; ++j)
        Ac2[j] = -__expf(A_log[cg * 32 + w * 4 + j]) * 1.44269504f;

    const float4* del4 = (const float4*)(g_delta + (size_t)b * Ll * Nn);
    const float4* br4  = (const float4*)(g_Braw  + (size_t)b * Ll * Nn);
    const float* xcb   = g_xc + (size_t)b * Ll * Ee + cg * 32;

    float h[4][4];
    #pragma unroll
    for (int j = 0; j < 4; ++j)
        #pragma unroll
        for (int i = 0; i < 4; ++i) h[j][i] = 0.f;

    float dc = 0.f;
    bool do_cum = (cg == 0) && (tid < 128);

    for (int t0 = k * CS; t0 < (k + 1) * CS; t0 += 16) {
        #pragma unroll
        for (int i = 0; i < 2; ++i) {
            int idx = tid + i * 256;
            float4 d = del4[t0 * 32 + idx];
            float4 r = br4[t0 * 32 + idx];
            ((float4*)smd)[idx] = d;
            float4 p; p.x = d.x * r.x; p.y = d.y * r.y; p.z = d.z * r.z; p.w = d.w * r.w;
            ((float4*)smb)[idx] = p;
        }
        if (tid < 128) {
            int tt = tid >> 3, q = tid & 7;
            *(float4*)&smx[tt][q * 4] = *(const float4*)&xcb[(size_t)(t0 + tt) * Ee + q * 4];
        }
        __syncthreads();

        if (do_cum) {
            float* gout = g_cumd + (size_t)b * Ll * Nn + (size_t)t0 * Nn + tid;
            #pragma unroll
            for (int tl = 0; tl < 16; ++tl) { dc += smd[tl][tid]; gout[tl * 128] = dc; }
        }

        #pragma unroll
        for (int tb = 0; tb < 16; tb += 4) {
            #pragma unroll
            for (int tt = 0; tt < 4; ++tt) {
                int t = tb + tt;
                float4 d4 = *(float4*)&smd[t][ln * 4];
                float4 b4 = *(float4*)&smb[t][ln * 4];
                float4 x4 = *(float4*)&smx[t][w * 4];
                float dn[4] = {d4.x, d4.y, d4.z, d4.w};
                float bn[4] = {b4.x, b4.y, b4.z, b4.w};
                float xs[4] = {x4.x, x4.y, x4.z, x4.w};
                #pragma unroll
                for (int j = 0; j < 4; ++j) {
                    #pragma unroll
                    for (int i = 0; i < 4; ++i) {
                        float e = ex2f(dn[i] * Ac2[j]);
                        h[j][i] = fmaf(e, h[j][i], bn[i] * xs[j]);
                    }
                    smP[tt][ln][w * 4 + j] = (h[j][0] + h[j][1]) + (h[j][2] + h[j][3]);
                }
            }
            __syncthreads();
            if (tid < 128) {
                int tt = tid >> 5, c = tid & 31;
                float s = 0.f;
                #pragma unroll
                for (int q = 0; q < 32; ++q) s += smP[tt][q][c];
                int t = t0 + tb + tt;
                g_S[(size_t)b * Ll * Hh + (size_t)t * Hh + cg * 32 + c] = s;
            }
            __syncthreads();
        }
    }

    size_t base = ((size_t)(b * CH + k) * Nn + ln * 4) * Hh + cg * 32 + w * 4;
    #pragma unroll
    for (int i = 0; i < 4; ++i) {
        float4 v; v.x = h[0][i]; v.y = h[1][i]; v.z = h[2][i]; v.w = h[3][i];
        *(float4*)&g_hE[base + (size_t)i * Hh] = v;
    }
}

// ---------------- Pass 2: inter-chunk state chain ----------------
__global__ __launch_bounds__(256) void chain_kernel(const float* __restrict__ A_log)
{
    int g = blockIdx.x * 256 + threadIdx.x;        // 0 .. 65535
    int c = g & 127, n = (g >> 7) & 127, b = g >> 14;
    float Ac2 = -__expf(A_log[c]) * 1.44269504f;
    const float* cd = g_cumd + (size_t)b * Ll * Nn + n;
    float h = 0.f;
    #pragma unroll
    for (int k = 0; k < CH; ++k) {
        size_t idx = ((size_t)(b * CH + k) * Nn + n) * Hh + c;
        g_h0[idx] = h;
        float dec = ex2f(Ac2 * cd[(size_t)(k * CS + CS - 1) * Nn]);
        h = fmaf(dec, h, g_hE[idx]);
    }
}

// ---------------- Pass 3: fixup + combine ----------------
#define T3 8
__global__ __launch_bounds__(256) void fixup_kernel(
    const float* __restrict__ A_log, const float* __restrict__ Dv,
    const float* __restrict__ u)
{
    __shared__ __align__(16) float smh[32][128];
    __shared__ __align__(16) float smc[T3][128];

    int b = blockIdx.z, k = blockIdx.y, tg = blockIdx.x;
    int t0 = k * CS + tg * T3;
    int tid = threadIdx.x;
    int c = tid & 127, th = tid >> 7;

    float acc[4] = {0.f, 0.f, 0.f, 0.f};

    if (k > 0) {
        float Ac2 = -__expf(A_log[c]) * 1.44269504f;
        #pragma unroll
        for (int i = 0; i < 4; ++i) {
            int idx = tid + i * 256;
            int tt = idx >> 7, n = idx & 127;
            smc[tt][n] = g_cumd[(size_t)b * Ll * Nn + (size_t)(t0 + tt) * Nn + n];
        }
        const float4* h0p = (const float4*)(g_h0 + ((size_t)(b * CH + k) * Nn) * Hh);
        #pragma unroll
        for (int nb = 0; nb < 4; ++nb) {
            __syncthreads();
            #pragma unroll
            for (int i = 0; i < 4; ++i) {
                int idx = tid + i * 256;
                ((float4*)smh)[idx] = h0p[nb * 1024 + idx];
            }
            __syncthreads();
            #pragma unroll
            for (int n = 0; n < 32; ++n) {
                float hv = smh[n][c];
                #pragma unroll
                for (int j = 0; j < 4; ++j) {
                    float dl = smc[th * 4 + j][nb * 32 + n];
                    acc[j] = fmaf(ex2f(dl * Ac2), hv, acc[j]);
                }
            }
        }
    }

    #pragma unroll
    for (int j = 0; j < 4; ++j) {
        int t = t0 + th * 4 + j;
        size_t off = (size_t)b * Ll * Hh + (size_t)t * Hh + c;
        float S = g_S[off] + acc[j];
        float y = fmaf(S, g_C[off], Dv[c] * u[off]);
        g_y[off] = y * g_zs[off];
    }
}

// ---------------- launch ----------------
extern "C" void kernel_launch(void* const* d_in, const int* in_sizes, int n_in,
                              void* d_out, int out_size)
{
    const float* u      = (const float*)d_in[0];
    const float* W_in   = (const float*)d_in[1];
    const float* b_in   = (const float*)d_in[2];
    const float* conv_w = (const float*)d_in[3];
    const float* conv_b = (const float*)d_in[4];
    const float* W_x    = (const float*)d_in[5];
    const float* b_x    = (const float*)d_in[6];
    const float* A_log  = (const float*)d_in[7];
    const float* Dv     = (const float*)d_in[8];
    const float* W_out  = (const float*)d_in[9];
    const float* b_out  = (const float*)d_in[10];
    float* out = (float*)d_out;

    float* gx; cudaGetSymbolAddress((void**)&gx, g_x);      // just to force no-elide (no-op)
    (void)gx;

    dim3 blk(256);
    gemm_tc<1><<<dim3(ML / 128, 256 / 64), blk>>>(u, W_in, b_in, nullptr, 256);
    conv_kernel<<<(Bb * Ll * Ee + 255) / 256, blk>>>(conv_w, conv_b);
    {
        float* gxc; cudaGetSymbolAddress((void**)&gxc, g_xc);
        gemm_tc<2><<<dim3(ML / 128, 384 / 64), blk>>>(gxc, W_x, b_x, nullptr, 384);
    }
    scan_local_kernel<<<dim3(4, CH, Bb), blk>>>(A_log);
    chain_kernel<<<dim3(Bb * Nn * Hh / 256), blk>>>(A_log);
    fixup_kernel<<<dim3(CS / T3, CH, Bb), blk>>>(A_log, Dv, u);
    {
        float* gy; cudaGetSymbolAddress((void**)&gy, g_y);
        gemm_tc<3><<<dim3(ML / 128, 128 / 64), blk>>>(gy, W_out, b_out, out, 128);
    }
}

// round 6
// speedup vs baseline: 1.5231x; 1.5231x over previous
#include <cuda_runtime.h>

#define Bb 4
#define Ll 1024
#define Hh 128
#define Ee 128
#define Nn 128
#define ML (Bb*Ll)   // 4096
#define CH 32        // number of L-chunks
#define CS 32        // chunk size (CH*CS == Ll)

// ---------------- scratch (device globals: no allocations allowed) ----------------
__device__ float g_x[Bb*Ll*Ee];      // pre-conv x
__device__ float g_zs[Bb*Ll*Ee];     // silu(z)
__device__ float g_xc[Bb*Ll*Ee];     // post-conv silu(x)
__device__ float g_delta[Bb*Ll*Nn];  // softplus'd
__device__ float g_Braw[Bb*Ll*Nn];
__device__ float g_C[Bb*Ll*Hh];
__device__ float g_y[Bb*Ll*Hh];      // gated scan output (input to GEMM3)
__device__ float g_S[Bb*Ll*Hh];      // local (then full) n-sums
__device__ float g_cumd[Bb*Ll*Nn];   // within-chunk inclusive cumsum of delta [b][t][n]
__device__ float g_hE[Bb*CH*Nn*Hh];  // chunk-end local states [b][k][n][c]
__device__ float g_h0[Bb*CH*Nn*Hh];  // chunk-start true states [b][k][n][c]

__device__ __forceinline__ float silu_(float x){ return x / (1.f + __expf(-x)); }
__device__ __forceinline__ float softplus_(float x){ return x > 20.f ? x : log1pf(__expf(x)); }
__device__ __forceinline__ float ex2f(float x){ float r; asm("ex2.approx.ftz.f32 %0, %1;" : "=f"(r) : "f"(x)); return r; }

// ---------------- 64x64-tile SGEMM, K=128, A-transposed smem, fused epilogues ------
// Inner loop per k: 1 LDS.128 (A frag) + 1 LDS.128 (B frag) + 16 FMA -> FMA-bound.
template<int EPI>
__global__ __launch_bounds__(256) void gemm_kernel(
    const float* __restrict__ Ain, const float* __restrict__ Wp,
    const float* __restrict__ bias, float* __restrict__ Cout, int ldN)
{
    __shared__ __align__(16) float At[64][68];   // [k][row]  (transposed A chunk)
    __shared__ __align__(16) float Bs[64][68];   // [k][col]
    const float* Ap = (EPI == 1) ? Ain : (EPI == 2 ? g_xc : g_y);

    int tid = threadIdx.x;
    int ty = tid >> 4, tx = tid & 15;
    int row0 = blockIdx.x * 64;
    int col0 = blockIdx.y * 64;

    float acc[4][4];
    #pragma unroll
    for (int i = 0; i < 4; i++)
        #pragma unroll
        for (int j = 0; j < 4; j++) acc[i][j] = 0.f;

    #pragma unroll 1
    for (int kb = 0; kb < 2; ++kb) {
        // stage A transposed: 64 rows x 64 k (1024 float4 slots)
        // warp holds kq fixed, r spans 32 consecutive -> STS.32 conflict-free (pitch 68)
        #pragma unroll
        for (int i = 0; i < 4; ++i) {
            int f = tid + i * 256;
            int kq = f >> 6, r = f & 63;
            float4 v = *(const float4*)&Ap[(size_t)(row0 + r) * 128 + kb * 64 + kq * 4];
            At[kq * 4 + 0][r] = v.x;
            At[kq * 4 + 1][r] = v.y;
            At[kq * 4 + 2][r] = v.z;
            At[kq * 4 + 3][r] = v.w;
        }
        // stage B: 64 k x 64 cols (1024 float4 slots), STS.128 conflict-free
        #pragma unroll
        for (int i = 0; i < 4; ++i) {
            int f = tid + i * 256;
            int k = f >> 4, q = f & 15;
            *(float4*)&Bs[k][q * 4] =
                *(const float4*)&Wp[(size_t)(kb * 64 + k) * ldN + col0 + q * 4];
        }
        __syncthreads();
        #pragma unroll 16
        for (int k = 0; k < 64; ++k) {
            float4 av = *(float4*)&At[k][ty * 4];   // broadcast across tx
            float4 bv = *(float4*)&Bs[k][tx * 4];   // conflict-free across lanes
            acc[0][0] = fmaf(av.x, bv.x, acc[0][0]); acc[0][1] = fmaf(av.x, bv.y, acc[0][1]);
            acc[0][2] = fmaf(av.x, bv.z, acc[0][2]); acc[0][3] = fmaf(av.x, bv.w, acc[0][3]);
            acc[1][0] = fmaf(av.y, bv.x, acc[1][0]); acc[1][1] = fmaf(av.y, bv.y, acc[1][1]);
            acc[1][2] = fmaf(av.y, bv.z, acc[1][2]); acc[1][3] = fmaf(av.y, bv.w, acc[1][3]);
            acc[2][0] = fmaf(av.z, bv.x, acc[2][0]); acc[2][1] = fmaf(av.z, bv.y, acc[2][1]);
            acc[2][2] = fmaf(av.z, bv.z, acc[2][2]); acc[2][3] = fmaf(av.z, bv.w, acc[2][3]);
            acc[3][0] = fmaf(av.w, bv.x, acc[3][0]); acc[3][1] = fmaf(av.w, bv.y, acc[3][1]);
            acc[3][2] = fmaf(av.w, bv.z, acc[3][2]); acc[3][3] = fmaf(av.w, bv.w, acc[3][3]);
        }
        __syncthreads();
    }

    // epilogue: thread owns rows row0+ty*4+{0..3}, cols col0+tx*4+{0..3} (float4 stores)
    int col = col0 + tx * 4;
    float4 bv = *(const float4*)&bias[col];
    #pragma unroll
    for (int i = 0; i < 4; ++i) {
        int row = row0 + ty * 4 + i;
        float4 v;
        v.x = acc[i][0] + bv.x; v.y = acc[i][1] + bv.y;
        v.z = acc[i][2] + bv.z; v.w = acc[i][3] + bv.w;
        if (EPI == 1) {
            if (col < 128) {
                *(float4*)&g_x[(size_t)row * 128 + col] = v;
            } else {
                float4 s; s.x = silu_(v.x); s.y = silu_(v.y); s.z = silu_(v.z); s.w = silu_(v.w);
                *(float4*)&g_zs[(size_t)row * 128 + col - 128] = s;
            }
        } else if (EPI == 2) {
            if (col < 128) {
                float4 s; s.x = softplus_(v.x); s.y = softplus_(v.y);
                s.z = softplus_(v.z); s.w = softplus_(v.w);
                *(float4*)&g_delta[(size_t)row * 128 + col] = s;
            } else if (col < 256) {
                *(float4*)&g_Braw[(size_t)row * 128 + col - 128] = v;
            } else {
                *(float4*)&g_C[(size_t)row * 128 + col - 256] = v;
            }
        } else {
            *(float4*)&Cout[(size_t)row * 128 + col] = v;
        }
    }
}

// ---------------- depthwise conv3 (+bias, silu) ----------------
__global__ void conv_kernel(const float* __restrict__ cw, const float* __restrict__ cb)
{
    int idx = blockIdx.x * blockDim.x + threadIdx.x;
    if (idx >= Bb * Ll * Ee) return;
    int e = idx & 127;
    int t = (idx >> 7) & (Ll - 1);
    float w0 = cw[e * 3 + 0], w1 = cw[e * 3 + 1], w2 = cw[e * 3 + 2];
    float xm = g_x[idx];
    float xl = (t > 0)      ? g_x[idx - 128] : 0.f;
    float xr = (t < Ll - 1) ? g_x[idx + 128] : 0.f;
    float v = fmaf(w0, xl, fmaf(w1, xm, fmaf(w2, xr, cb[e])));
    g_xc[idx] = silu_(v);
}

// ---------------- Pass 1: per-chunk local scan (4n x 4c states per thread) ----------
__global__ __launch_bounds__(256) void scan_local_kernel(const float* __restrict__ A_log)
{
    __shared__ __align__(16) float smd[16][128];
    __shared__ __align__(16) float smb[16][128];
    __shared__ __align__(16) float smx[16][32];
    __shared__ float smP[4][32][33];

    int b  = blockIdx.z;
    int k  = blockIdx.y;
    int cg = blockIdx.x;
    int tid = threadIdx.x;
    int w = tid >> 5, ln = tid & 31;

    float Ac2[4];
    #pragma unroll
    for (int j = 0; j < 4; ++j)
        Ac2[j] = -__expf(A_log[cg * 32 + w * 4 + j]) * 1.44269504f;

    const float4* del4 = (const float4*)(g_delta + (size_t)b * Ll * Nn);
    const float4* br4  = (const float4*)(g_Braw  + (size_t)b * Ll * Nn);
    const float* xcb   = g_xc + (size_t)b * Ll * Ee + cg * 32;

    float h[4][4];
    #pragma unroll
    for (int j = 0; j < 4; ++j)
        #pragma unroll
        for (int i = 0; i < 4; ++i) h[j][i] = 0.f;

    float dc = 0.f;
    bool do_cum = (cg == 0) && (tid < 128);

    for (int t0 = k * CS; t0 < (k + 1) * CS; t0 += 16) {
        #pragma unroll
        for (int i = 0; i < 2; ++i) {
            int idx = tid + i * 256;
            float4 d = del4[t0 * 32 + idx];
            float4 r = br4[t0 * 32 + idx];
            ((float4*)smd)[idx] = d;
            float4 p; p.x = d.x * r.x; p.y = d.y * r.y; p.z = d.z * r.z; p.w = d.w * r.w;
            ((float4*)smb)[idx] = p;
        }
        if (tid < 128) {
            int tt = tid >> 3, q = tid & 7;
            *(float4*)&smx[tt][q * 4] = *(const float4*)&xcb[(size_t)(t0 + tt) * Ee + q * 4];
        }
        __syncthreads();

        if (do_cum) {
            float* gout = g_cumd + (size_t)b * Ll * Nn + (size_t)t0 * Nn + tid;
            #pragma unroll
            for (int tl = 0; tl < 16; ++tl) { dc += smd[tl][tid]; gout[tl * 128] = dc; }
        }

        #pragma unroll
        for (int tb = 0; tb < 16; tb += 4) {
            #pragma unroll
            for (int tt = 0; tt < 4; ++tt) {
                int t = tb + tt;
                float4 d4 = *(float4*)&smd[t][ln * 4];
                float4 b4 = *(float4*)&smb[t][ln * 4];
                float4 x4 = *(float4*)&smx[t][w * 4];
                float dn[4] = {d4.x, d4.y, d4.z, d4.w};
                float bn[4] = {b4.x, b4.y, b4.z, b4.w};
                float xs[4] = {x4.x, x4.y, x4.z, x4.w};
                #pragma unroll
                for (int j = 0; j < 4; ++j) {
                    #pragma unroll
                    for (int i = 0; i < 4; ++i) {
                        float e = ex2f(dn[i] * Ac2[j]);
                        h[j][i] = fmaf(e, h[j][i], bn[i] * xs[j]);
                    }
                    smP[tt][ln][w * 4 + j] = (h[j][0] + h[j][1]) + (h[j][2] + h[j][3]);
                }
            }
            __syncthreads();
            if (tid < 128) {
                int tt = tid >> 5, c = tid & 31;
                float s = 0.f;
                #pragma unroll
                for (int q = 0; q < 32; ++q) s += smP[tt][q][c];
                int t = t0 + tb + tt;
                g_S[(size_t)b * Ll * Hh + (size_t)t * Hh + cg * 32 + c] = s;
            }
            __syncthreads();
        }
    }

    size_t base = ((size_t)(b * CH + k) * Nn + ln * 4) * Hh + cg * 32 + w * 4;
    #pragma unroll
    for (int i = 0; i < 4; ++i) {
        float4 v; v.x = h[0][i]; v.y = h[1][i]; v.z = h[2][i]; v.w = h[3][i];
        *(float4*)&g_hE[base + (size_t)i * Hh] = v;
    }
}

// ---------------- Pass 2: inter-chunk state chain ----------------
__global__ __launch_bounds__(256) void chain_kernel(const float* __restrict__ A_log)
{
    int g = blockIdx.x * 256 + threadIdx.x;        // 0 .. 65535
    int c = g & 127, n = (g >> 7) & 127, b = g >> 14;
    float Ac2 = -__expf(A_log[c]) * 1.44269504f;
    const float* cd = g_cumd + (size_t)b * Ll * Nn + n;
    float h = 0.f;
    #pragma unroll
    for (int k = 0; k < CH; ++k) {
        size_t idx = ((size_t)(b * CH + k) * Nn + n) * Hh + c;
        g_h0[idx] = h;
        float dec = ex2f(Ac2 * cd[(size_t)(k * CS + CS - 1) * Nn]);
        h = fmaf(dec, h, g_hE[idx]);
    }
}

// ---------------- Pass 3: fixup + combine ----------------
#define T3 8
__global__ __launch_bounds__(256) void fixup_kernel(
    const float* __restrict__ A_log, const float* __restrict__ Dv,
    const float* __restrict__ u)
{
    __shared__ __align__(16) float smh[32][128];
    __shared__ __align__(16) float smc[T3][128];

    int b = blockIdx.z, k = blockIdx.y, tg = blockIdx.x;
    int t0 = k * CS + tg * T3;
    int tid = threadIdx.x;
    int c = tid & 127, th = tid >> 7;

    float acc[4] = {0.f, 0.f, 0.f, 0.f};

    if (k > 0) {
        float Ac2 = -__expf(A_log[c]) * 1.44269504f;
        #pragma unroll
        for (int i = 0; i < 4; ++i) {
            int idx = tid + i * 256;
            int tt = idx >> 7, n = idx & 127;
            smc[tt][n] = g_cumd[(size_t)b * Ll * Nn + (size_t)(t0 + tt) * Nn + n];
        }
        const float4* h0p = (const float4*)(g_h0 + ((size_t)(b * CH + k) * Nn) * Hh);
        #pragma unroll
        for (int nb = 0; nb < 4; ++nb) {
            __syncthreads();
            #pragma unroll
            for (int i = 0; i < 4; ++i) {
                int idx = tid + i * 256;
                ((float4*)smh)[idx] = h0p[nb * 1024 + idx];
            }
            __syncthreads();
            #pragma unroll
            for (int n = 0; n < 32; ++n) {
                float hv = smh[n][c];
                #pragma unroll
                for (int j = 0; j < 4; ++j) {
                    float dl = smc[th * 4 + j][nb * 32 + n];
                    acc[j] = fmaf(ex2f(dl * Ac2), hv, acc[j]);
                }
            }
        }
    }

    #pragma unroll
    for (int j = 0; j < 4; ++j) {
        int t = t0 + th * 4 + j;
        size_t off = (size_t)b * Ll * Hh + (size_t)t * Hh + c;
        float S = g_S[off] + acc[j];
        float y = fmaf(S, g_C[off], Dv[c] * u[off]);
        g_y[off] = y * g_zs[off];
    }
}

// ---------------- launch ----------------
extern "C" void kernel_launch(void* const* d_in, const int* in_sizes, int n_in,
                              void* d_out, int out_size)
{
    const float* u      = (const float*)d_in[0];
    const float* W_in   = (const float*)d_in[1];
    const float* b_in   = (const float*)d_in[2];
    const float* conv_w = (const float*)d_in[3];
    const float* conv_b = (const float*)d_in[4];
    const float* W_x    = (const float*)d_in[5];
    const float* b_x    = (const float*)d_in[6];
    const float* A_log  = (const float*)d_in[7];
    const float* Dv     = (const float*)d_in[8];
    const float* W_out  = (const float*)d_in[9];
    const float* b_out  = (const float*)d_in[10];
    float* out = (float*)d_out;

    dim3 blk(256);
    gemm_kernel<1><<<dim3(ML / 64, 256 / 64), blk>>>(u, W_in, b_in, nullptr, 256);
    conv_kernel<<<(Bb * Ll * Ee + 255) / 256, blk>>>(conv_w, conv_b);
    gemm_kernel<2><<<dim3(ML / 64, 384 / 64), blk>>>(nullptr, W_x, b_x, nullptr, 384);
    scan_local_kernel<<<dim3(4, CH, Bb), blk>>>(A_log);
    chain_kernel<<<dim3(Bb * Nn * Hh / 256), blk>>>(A_log);
    fixup_kernel<<<dim3(CS / T3, CH, Bb), blk>>>(A_log, Dv, u);
    gemm_kernel<3><<<dim3(ML / 64, 128 / 64), blk>>>(nullptr, W_out, b_out, out, 128);
}